// round 1
// baseline (speedup 1.0000x reference)
#include <cuda_runtime.h>
#include <math.h>

#define DD 512
#define BATCH 8
#define SEQ 2048

#define BM 128
#define BN 128
#define BK 16
// 256 threads, each computes 8x8

// ---------------- scratch (device globals; no allocation) ----------------
__device__ float g_Q[BATCH * SEQ * DD];
__device__ float g_K[BATCH * SEQ * DD];
__device__ float g_V[BATCH * SEQ * DD];
__device__ float g_S[(size_t)BATCH * SEQ * SEQ];   // 128 MiB scores scratch
__device__ float g_A[BATCH * SEQ * DD];            // FTT + FTS
__device__ float g_C[BATCH * SEQ * DD];            // FSS + FST

// ---------------------------------------------------------------------------
// NT GEMM: C[m,n] = sum_k A[m,k] * B[n,k]   (both operands K-contiguous)
// MODE 0: C = acc + bias[n]                  (projection)
// MODE 1: C = acc * alpha                    (scores)
// MODE 2: C = acc + Extra[m,n]               (final, residual add)
// ---------------------------------------------------------------------------
template <int MODE>
__global__ __launch_bounds__(256, 2)
void gemm_nt_kernel(const float* __restrict__ Aall,
                    const float* __restrict__ Ball,
                    float* __restrict__ Call,
                    const float* __restrict__ Extra,
                    int M, int N, int K,
                    long long strideA, long long strideB, long long strideC,
                    long long strideE, float alpha)
{
    const float* A = Aall + (long long)blockIdx.z * strideA;
    const float* B = Ball + (long long)blockIdx.z * strideB;
    float*       C = Call + (long long)blockIdx.z * strideC;
    const float* E = (MODE == 2) ? (Extra + (long long)blockIdx.z * strideE) : Extra;

    __shared__ float As[BK][BM];
    __shared__ float Bs[BK][BN];

    const int tid = threadIdx.x;
    const int tx = tid & 15;        // n-dim
    const int ty = tid >> 4;        // m-dim
    const int m0 = blockIdx.y * BM;
    const int n0 = blockIdx.x * BN;

    float acc[8][8];
    #pragma unroll
    for (int i = 0; i < 8; i++)
        #pragma unroll
        for (int j = 0; j < 8; j++) acc[i][j] = 0.f;

    float ar[8], br[8];

    for (int k0 = 0; k0 < K; k0 += BK) {
        // A tile: BM rows x BK cols, K-contiguous -> transpose into As[k][m]
        #pragma unroll
        for (int it = 0; it < 2; it++) {
            int lin = tid + it * 256;          // 0..511
            int row = lin >> 2;                // 0..127
            int c4  = (lin & 3) * 4;           // 0,4,8,12
            float4 v = *(const float4*)&A[(long long)(m0 + row) * K + k0 + c4];
            As[c4 + 0][row] = v.x;
            As[c4 + 1][row] = v.y;
            As[c4 + 2][row] = v.z;
            As[c4 + 3][row] = v.w;
        }
        // B tile: BN rows x BK cols, K-contiguous -> Bs[k][n]
        #pragma unroll
        for (int it = 0; it < 2; it++) {
            int lin = tid + it * 256;
            int row = lin >> 2;
            int c4  = (lin & 3) * 4;
            float4 v = *(const float4*)&B[(long long)(n0 + row) * K + k0 + c4];
            Bs[c4 + 0][row] = v.x;
            Bs[c4 + 1][row] = v.y;
            Bs[c4 + 2][row] = v.z;
            Bs[c4 + 3][row] = v.w;
        }
        __syncthreads();

        #pragma unroll
        for (int k = 0; k < BK; k++) {
            *(float4*)&ar[0] = *(const float4*)&As[k][ty * 8];
            *(float4*)&ar[4] = *(const float4*)&As[k][ty * 8 + 4];
            *(float4*)&br[0] = *(const float4*)&Bs[k][tx * 8];
            *(float4*)&br[4] = *(const float4*)&Bs[k][tx * 8 + 4];
            #pragma unroll
            for (int i = 0; i < 8; i++)
                #pragma unroll
                for (int j = 0; j < 8; j++)
                    acc[i][j] += ar[i] * br[j];
        }
        __syncthreads();
    }

    #pragma unroll
    for (int i = 0; i < 8; i++) {
        int m = m0 + ty * 8 + i;
        #pragma unroll
        for (int j = 0; j < 8; j++) {
            int n = n0 + tx * 8 + j;
            float c = acc[i][j];
            if (MODE == 0) c += Extra[n];
            if (MODE == 1) c *= alpha;
            if (MODE == 2) c += E[(long long)m * N + n];
            C[(long long)m * N + n] = c;
        }
    }
}

// ---------------------------------------------------------------------------
// NN GEMM: C[m,n] (+)= sum_k A[m,k] * B[k,n]   (A K-contig, B N-contig)
// ---------------------------------------------------------------------------
__global__ __launch_bounds__(256, 2)
void gemm_nn_kernel(const float* __restrict__ Aall,
                    const float* __restrict__ Ball,
                    float* __restrict__ Call,
                    int M, int N, int K,
                    long long strideA, long long strideB, long long strideC,
                    int accumulate)
{
    const float* A = Aall + (long long)blockIdx.z * strideA;
    const float* B = Ball + (long long)blockIdx.z * strideB;
    float*       C = Call + (long long)blockIdx.z * strideC;

    __shared__ float As[BK][BM];
    __shared__ float Bs[BK][BN];

    const int tid = threadIdx.x;
    const int tx = tid & 15;
    const int ty = tid >> 4;
    const int m0 = blockIdx.y * BM;
    const int n0 = blockIdx.x * BN;

    float acc[8][8];
    #pragma unroll
    for (int i = 0; i < 8; i++)
        #pragma unroll
        for (int j = 0; j < 8; j++) acc[i][j] = 0.f;

    float ar[8], br[8];

    for (int k0 = 0; k0 < K; k0 += BK) {
        #pragma unroll
        for (int it = 0; it < 2; it++) {
            int lin = tid + it * 256;
            int row = lin >> 2;
            int c4  = (lin & 3) * 4;
            float4 v = *(const float4*)&A[(long long)(m0 + row) * K + k0 + c4];
            As[c4 + 0][row] = v.x;
            As[c4 + 1][row] = v.y;
            As[c4 + 2][row] = v.z;
            As[c4 + 3][row] = v.w;
        }
        // B tile: BK rows x BN cols, N-contiguous -> direct coalesced
        #pragma unroll
        for (int it = 0; it < 2; it++) {
            int lin = tid + it * 256;          // 0..511
            int row = lin >> 5;                // 0..15
            int c4  = (lin & 31) * 4;          // 0..124
            float4 v = *(const float4*)&B[(long long)(k0 + row) * N + n0 + c4];
            *(float4*)&Bs[row][c4] = v;
        }
        __syncthreads();

        #pragma unroll
        for (int k = 0; k < BK; k++) {
            *(float4*)&ar[0] = *(const float4*)&As[k][ty * 8];
            *(float4*)&ar[4] = *(const float4*)&As[k][ty * 8 + 4];
            *(float4*)&br[0] = *(const float4*)&Bs[k][tx * 8];
            *(float4*)&br[4] = *(const float4*)&Bs[k][tx * 8 + 4];
            #pragma unroll
            for (int i = 0; i < 8; i++)
                #pragma unroll
                for (int j = 0; j < 8; j++)
                    acc[i][j] += ar[i] * br[j];
        }
        __syncthreads();
    }

    #pragma unroll
    for (int i = 0; i < 8; i++) {
        int m = m0 + ty * 8 + i;
        #pragma unroll
        for (int j = 0; j < 8; j++) {
            int n = n0 + tx * 8 + j;
            long long idx = (long long)m * N + n;
            C[idx] = accumulate ? (C[idx] + acc[i][j]) : acc[i][j];
        }
    }
}

// ---------------------------------------------------------------------------
// Row softmax over 2048 columns; one block (256 threads) per row.
// ---------------------------------------------------------------------------
__global__ __launch_bounds__(256)
void softmax_rows_kernel(float* __restrict__ S)
{
    float* row = S + (long long)blockIdx.x * SEQ;
    const int tid = threadIdx.x;

    float vals[8];
    float m = -INFINITY;
    #pragma unroll
    for (int i = 0; i < 8; i++) {
        vals[i] = row[tid + i * 256];
        m = fmaxf(m, vals[i]);
    }

    __shared__ float red[256];
    red[tid] = m;
    __syncthreads();
    #pragma unroll
    for (int s = 128; s > 0; s >>= 1) {
        if (tid < s) red[tid] = fmaxf(red[tid], red[tid + s]);
        __syncthreads();
    }
    m = red[0];
    __syncthreads();

    float sum = 0.f;
    #pragma unroll
    for (int i = 0; i < 8; i++) {
        vals[i] = expf(vals[i] - m);
        sum += vals[i];
    }
    red[tid] = sum;
    __syncthreads();
    #pragma unroll
    for (int s = 128; s > 0; s >>= 1) {
        if (tid < s) red[tid] += red[tid + s];
        __syncthreads();
    }
    float inv = 1.0f / red[0];

    #pragma unroll
    for (int i = 0; i < 8; i++)
        row[tid + i * 256] = vals[i] * inv;
}

// ---------------------------------------------------------------------------
extern "C" void kernel_launch(void* const* d_in, const int* in_sizes, int n_in,
                              void* d_out, int out_size)
{
    const float* Itime   = (const float*)d_in[0];
    const float* Ispace  = (const float*)d_in[1];
    const float* xorigin = (const float*)d_in[2];
    const float* Wq      = (const float*)d_in[3];
    const float* bq      = (const float*)d_in[4];
    const float* Wk      = (const float*)d_in[5];
    const float* bk      = (const float*)d_in[6];
    const float* Wv      = (const float*)d_in[7];
    const float* bv      = (const float*)d_in[8];
    float* out = (float*)d_out;

    float *Q, *K, *V, *S, *Abuf, *Cbuf;
    cudaGetSymbolAddress((void**)&Q,    g_Q);
    cudaGetSymbolAddress((void**)&K,    g_K);
    cudaGetSymbolAddress((void**)&V,    g_V);
    cudaGetSymbolAddress((void**)&S,    g_S);
    cudaGetSymbolAddress((void**)&Abuf, g_A);
    cudaGetSymbolAddress((void**)&Cbuf, g_C);

    const dim3 thr(256);
    const float scale = 0.044194173824159216f;  // 1/sqrt(512)
    const long long sQKV = (long long)SEQ * DD;         // per-batch Q/K/V stride
    const long long sS   = (long long)SEQ * SEQ;        // per-batch scores stride
    const int MPROJ = BATCH * SEQ;                       // 16384

    struct Blk { const float* q; const float* kv; int w; float* F; int acc; };
    const Blk blks[4] = {
        { Itime,  Itime,  0, Abuf, 0 },   // FTT
        { Itime,  Ispace, 2, Abuf, 1 },   // FTS  (accumulate into A)
        { Ispace, Ispace, 1, Cbuf, 0 },   // FSS
        { Ispace, Itime,  3, Cbuf, 1 },   // FST  (accumulate into C)
    };

    for (int i = 0; i < 4; i++) {
        const Blk& b = blks[i];
        const float* wq = Wq + (size_t)b.w * DD * DD;
        const float* wk = Wk + (size_t)b.w * DD * DD;
        const float* wv = Wv + (size_t)b.w * DD * DD;

        // Projections: (B*N, D) x (D, D)^T + bias
        dim3 gproj(DD / BN, MPROJ / BM, 1);
        gemm_nt_kernel<0><<<gproj, thr>>>(b.q,  wq, Q, bq + b.w * DD,
                                          MPROJ, DD, DD, 0, 0, 0, 0, 1.0f);
        gemm_nt_kernel<0><<<gproj, thr>>>(b.kv, wk, K, bk + b.w * DD,
                                          MPROJ, DD, DD, 0, 0, 0, 0, 1.0f);
        gemm_nt_kernel<0><<<gproj, thr>>>(b.kv, wv, V, bv + b.w * DD,
                                          MPROJ, DD, DD, 0, 0, 0, 0, 1.0f);

        // Scores: S[b] = scale * Q[b] @ K[b]^T
        dim3 gsc(SEQ / BN, SEQ / BM, BATCH);
        gemm_nt_kernel<1><<<gsc, thr>>>(Q, K, S, nullptr,
                                        SEQ, SEQ, DD, sQKV, sQKV, sS, 0, scale);

        // Softmax over each row
        softmax_rows_kernel<<<BATCH * SEQ, thr>>>(S);

        // F[b] (+)= P[b] @ V[b]
        dim3 gpv(DD / BN, SEQ / BM, BATCH);
        gemm_nn_kernel<<<gpv, thr>>>(S, V, b.F,
                                     SEQ, DD, SEQ, sS, sQKV, sQKV, b.acc);
    }

    // out[b] = A[b] @ C[b]^T + x_origin[b]
    dim3 gfin(SEQ / BN, SEQ / BM, BATCH);
    gemm_nt_kernel<2><<<gfin, thr>>>(Abuf, Cbuf, out, xorigin,
                                     SEQ, SEQ, DD, sQKV, sQKV, sS, sS, 1.0f);
}

// round 3
// speedup vs baseline: 7.6991x; 7.6991x over previous
#include <cuda_runtime.h>
#include <cuda_fp16.h>
#include <stdint.h>
#include <math.h>

#define DD 512
#define BATCH 8
#define SEQ 2048
#define MTOT (BATCH * SEQ)   // 16384

#define TM 128
#define TN 128
#define BKK 64
#define NTH 256

#define STG_BYTES 32768           // A tile 16KB + B tile 16KB
#define SMEM_TOTAL 65536          // 2 stages (transpose staging reuses this)

// ---------------- scratch (device globals; no allocation) ----------------
__device__ __align__(1024) __half g_ITh[MTOT * DD];
__device__ __align__(1024) __half g_ISh[MTOT * DD];
__device__ __align__(1024) __half g_Wqh[4 * DD * DD];
__device__ __align__(1024) __half g_Wkh[4 * DD * DD];
__device__ __align__(1024) __half g_Wvh[4 * DD * DD];
__device__ __align__(1024) __half g_Qh[MTOT * DD];
__device__ __align__(1024) __half g_Kh[MTOT * DD];
__device__ __align__(1024) __half g_Vth[MTOT * DD];    // [feature][token] transposed
__device__ __align__(1024) __half g_S[(size_t)BATCH * SEQ * SEQ];
__device__ __align__(1024) __half g_P[(size_t)BATCH * SEQ * SEQ];
__device__ __align__(1024) float  g_A[MTOT * DD];
__device__ __align__(1024) float  g_C[MTOT * DD];
__device__ __align__(1024) __half g_Ah[MTOT * DD];
__device__ __align__(1024) __half g_Ch[MTOT * DD];

// ---------------- helpers ----------------
__device__ __forceinline__ uint32_t s2u(const void* p) {
    uint32_t a;
    asm("{ .reg .u64 t; cvta.to.shared.u64 t, %1; cvt.u32.u64 %0, t; }" : "=r"(a) : "l"(p));
    return a;
}
__device__ __forceinline__ void cp16(uint32_t dst, const void* src) {
    asm volatile("cp.async.cg.shared.global [%0], [%1], 16;" :: "r"(dst), "l"(src));
}
__device__ __forceinline__ void cp_commit() { asm volatile("cp.async.commit_group;" ::: "memory"); }
template <int N> __device__ __forceinline__ void cp_wait() {
    asm volatile("cp.async.wait_group %0;" :: "n"(N) : "memory");
}
__device__ __forceinline__ void ldsm4(uint32_t* d, uint32_t addr) {
    asm volatile("ldmatrix.sync.aligned.m8n8.x4.shared.b16 {%0,%1,%2,%3}, [%4];"
                 : "=r"(d[0]), "=r"(d[1]), "=r"(d[2]), "=r"(d[3]) : "r"(addr));
}
__device__ __forceinline__ void mma16816(float* c, const uint32_t* a, uint32_t b0, uint32_t b1) {
    asm volatile(
        "mma.sync.aligned.m16n8k16.row.col.f32.f16.f16.f32 "
        "{%0,%1,%2,%3},{%4,%5,%6,%7},{%8,%9},{%0,%1,%2,%3};"
        : "+f"(c[0]), "+f"(c[1]), "+f"(c[2]), "+f"(c[3])
        : "r"(a[0]), "r"(a[1]), "r"(a[2]), "r"(a[3]), "r"(b0), "r"(b1));
}

// ---------------------------------------------------------------------------
// NT GEMM: D[m,n] = sum_k A[m,k] * B[n,k]   (both fp16 K-contiguous), fp32 acc
// ---------------------------------------------------------------------------
enum { MODE_QK = 0, MODE_VT = 1, MODE_SC = 2, MODE_PV = 3, MODE_FIN = 4 };

template <int MODE>
__global__ __launch_bounds__(NTH, 2)
void hgemm(const __half* __restrict__ A, const __half* __restrict__ B,
           void* __restrict__ out, const float* __restrict__ X,
           int ldA, int ldB, int ldC, int K,
           long long strA, long long strB, long long strC,
           float alpha, int accflag)
{
    extern __shared__ __align__(16) char smem[];
    const uint32_t sbase = s2u(smem);
    const int tid  = threadIdx.x;
    const int lane = tid & 31;
    const int warp = tid >> 5;
    const int wm = warp & 1;          // 2 warps along m
    const int wn = warp >> 1;         // 4 warps along n
    const int z  = blockIdx.z;
    const int m0 = blockIdx.y * TM;
    const int n0 = blockIdx.x * TN;

    const __half* Ap = A + (size_t)z * strA;
    const __half* Bp = B + (size_t)z * strB;

    float acc[4][4][4];
    #pragma unroll
    for (int i = 0; i < 4; i++)
        #pragma unroll
        for (int j = 0; j < 4; j++)
            #pragma unroll
            for (int e = 0; e < 4; e++) acc[i][j][e] = 0.f;

    const int nK = K / BKK;

    auto load_stage = [&](int ck, int stg) {
        const int k0 = ck * BKK;
        const uint32_t sb = sbase + stg * STG_BYTES;
        #pragma unroll
        for (int t = 0; t < 4; t++) {               // A: 128 rows x 128B
            int id = tid + t * NTH;
            int r = id >> 3, c = id & 7;
            cp16(sb + r * 128 + (((c ^ (r & 7)) & 7) << 4),
                 Ap + (size_t)(m0 + r) * ldA + k0 + c * 8);
        }
        #pragma unroll
        for (int t = 0; t < 4; t++) {               // B: 128 rows x 128B
            int id = tid + t * NTH;
            int r = id >> 3, c = id & 7;
            cp16(sb + 16384 + r * 128 + (((c ^ (r & 7)) & 7) << 4),
                 Bp + (size_t)(n0 + r) * ldB + k0 + c * 8);
        }
        cp_commit();
    };

    load_stage(0, 0);

    for (int i = 0; i < nK; i++) {
        cp_wait<0>();
        __syncthreads();
        if (i + 1 < nK) load_stage(i + 1, (i + 1) & 1);

        const uint32_t sA = sbase + (i & 1) * STG_BYTES;
        const uint32_t sB = sA + 16384;

        #pragma unroll
        for (int s = 0; s < 4; s++) {
            uint32_t af[4][4];
            #pragma unroll
            for (int im = 0; im < 4; im++) {
                int row = wm * 64 + im * 16 + (lane & 15);
                int ch  = 2 * s + (lane >> 4);
                ldsm4(af[im], sA + row * 128 + (((ch ^ (row & 7)) & 7) << 4));
            }
            uint32_t bf[2][4];
            #pragma unroll
            for (int j2 = 0; j2 < 2; j2++) {
                int row = wn * 32 + j2 * 16 + ((lane >> 4) << 3) + (lane & 7);
                int ch  = 2 * s + ((lane >> 3) & 1);
                ldsm4(bf[j2], sB + row * 128 + (((ch ^ (row & 7)) & 7) << 4));
            }
            #pragma unroll
            for (int im = 0; im < 4; im++)
                #pragma unroll
                for (int jn = 0; jn < 4; jn++)
                    mma16816(acc[im][jn], af[im], bf[jn >> 1][(jn & 1) * 2],
                             bf[jn >> 1][(jn & 1) * 2 + 1]);
        }
        __syncthreads();
    }

    // ---------------- epilogue ----------------
    const int lm = lane >> 2;
    const int ln = (lane & 3) * 2;

    if (MODE == MODE_VT) {
        // stage transposed tile in smem: smem_t[n_local][m_local], stride 136
        __half* st = (__half*)smem;
        #pragma unroll
        for (int im = 0; im < 4; im++) {
            int ml = wm * 64 + im * 16 + lm;
            #pragma unroll
            for (int jn = 0; jn < 4; jn++) {
                int nl = wn * 32 + jn * 8 + ln;
                float b0 = X[n0 + nl], b1 = X[n0 + nl + 1];
                st[nl * 136 + ml]           = __float2half(acc[im][jn][0] + b0);
                st[(nl + 1) * 136 + ml]     = __float2half(acc[im][jn][1] + b1);
                st[nl * 136 + ml + 8]       = __float2half(acc[im][jn][2] + b0);
                st[(nl + 1) * 136 + ml + 8] = __float2half(acc[im][jn][3] + b1);
            }
        }
        __syncthreads();
        __half* O = (__half*)out;
        #pragma unroll
        for (int t = 0; t < 8; t++) {
            int idx = tid + t * NTH;             // 2048 chunks of 16B
            int r = idx >> 4, sgl = idx & 15;
            uint4 v = *(const uint4*)(st + r * 136 + sgl * 8);
            *(uint4*)(O + (size_t)(n0 + r) * ldC + m0 + sgl * 8) = v;
        }
        return;
    }

    #pragma unroll
    for (int im = 0; im < 4; im++) {
        int r0 = m0 + wm * 64 + im * 16 + lm;
        int r1 = r0 + 8;
        #pragma unroll
        for (int jn = 0; jn < 4; jn++) {
            int c = n0 + wn * 32 + jn * 8 + ln;
            float v0 = acc[im][jn][0], v1 = acc[im][jn][1];
            float v2 = acc[im][jn][2], v3 = acc[im][jn][3];
            if (MODE == MODE_QK) {
                __half* O = (__half*)out;
                float b0 = X[c], b1 = X[c + 1];
                *(__half2*)(O + (size_t)r0 * ldC + c) = __floats2half2_rn(v0 + b0, v1 + b1);
                *(__half2*)(O + (size_t)r1 * ldC + c) = __floats2half2_rn(v2 + b0, v3 + b1);
            } else if (MODE == MODE_SC) {
                __half* O = (__half*)out + (size_t)z * strC;
                *(__half2*)(O + (size_t)r0 * ldC + c) = __floats2half2_rn(v0 * alpha, v1 * alpha);
                *(__half2*)(O + (size_t)r1 * ldC + c) = __floats2half2_rn(v2 * alpha, v3 * alpha);
            } else if (MODE == MODE_PV) {
                float* O = (float*)out + (size_t)z * strC;
                size_t o0 = (size_t)r0 * ldC + c, o1 = (size_t)r1 * ldC + c;
                if (accflag) {
                    float2 p0 = *(float2*)(O + o0), p1 = *(float2*)(O + o1);
                    v0 += p0.x; v1 += p0.y; v2 += p1.x; v3 += p1.y;
                }
                *(float2*)(O + o0) = make_float2(v0, v1);
                *(float2*)(O + o1) = make_float2(v2, v3);
            } else {  // MODE_FIN
                float* O = (float*)out + (size_t)z * strC;
                const float* Xz = X + (size_t)z * strC;
                size_t o0 = (size_t)r0 * ldC + c, o1 = (size_t)r1 * ldC + c;
                float2 p0 = *(const float2*)(Xz + o0), p1 = *(const float2*)(Xz + o1);
                *(float2*)(O + o0) = make_float2(v0 + p0.x, v1 + p0.y);
                *(float2*)(O + o1) = make_float2(v2 + p1.x, v3 + p1.y);
            }
        }
    }
}

// ---------------------------------------------------------------------------
// fp32 -> fp16 convert
// ---------------------------------------------------------------------------
__global__ __launch_bounds__(256)
void tohalf_kernel(const float* __restrict__ src, __half* __restrict__ dst, int n4)
{
    int idx = blockIdx.x * blockDim.x + threadIdx.x;
    int stride = gridDim.x * blockDim.x;
    const float4* s4 = (const float4*)src;
    __half2* d2 = (__half2*)dst;
    for (int i = idx; i < n4; i += stride) {
        float4 v = s4[i];
        d2[i * 2]     = __floats2half2_rn(v.x, v.y);
        d2[i * 2 + 1] = __floats2half2_rn(v.z, v.w);
    }
}

// ---------------------------------------------------------------------------
// Row softmax over 2048 fp16 cols -> fp16 probabilities
// ---------------------------------------------------------------------------
__global__ __launch_bounds__(256)
void softmax_kernel(const __half* __restrict__ S, __half* __restrict__ P)
{
    const size_t base = (size_t)blockIdx.x * SEQ;
    const int tid = threadIdx.x;

    float vals[8];
    float m = -INFINITY;
    #pragma unroll
    for (int i = 0; i < 4; i++) {
        __half2 h = *(const __half2*)(S + base + tid * 2 + i * 512);
        vals[i * 2]     = __half2float(h.x);
        vals[i * 2 + 1] = __half2float(h.y);
        m = fmaxf(m, fmaxf(vals[i * 2], vals[i * 2 + 1]));
    }
    __shared__ float red[256];
    red[tid] = m;
    __syncthreads();
    #pragma unroll
    for (int s = 128; s > 0; s >>= 1) {
        if (tid < s) red[tid] = fmaxf(red[tid], red[tid + s]);
        __syncthreads();
    }
    m = red[0];
    __syncthreads();

    float sum = 0.f;
    #pragma unroll
    for (int i = 0; i < 8; i++) {
        vals[i] = expf(vals[i] - m);
        sum += vals[i];
    }
    red[tid] = sum;
    __syncthreads();
    #pragma unroll
    for (int s = 128; s > 0; s >>= 1) {
        if (tid < s) red[tid] += red[tid + s];
        __syncthreads();
    }
    float inv = 1.0f / red[0];

    #pragma unroll
    for (int i = 0; i < 4; i++) {
        *(__half2*)(P + base + tid * 2 + i * 512) =
            __floats2half2_rn(vals[i * 2] * inv, vals[i * 2 + 1] * inv);
    }
}

// ---------------------------------------------------------------------------
extern "C" void kernel_launch(void* const* d_in, const int* in_sizes, int n_in,
                              void* d_out, int out_size)
{
    const float* Itime   = (const float*)d_in[0];
    const float* Ispace  = (const float*)d_in[1];
    const float* xorigin = (const float*)d_in[2];
    const float* Wq      = (const float*)d_in[3];
    const float* bq      = (const float*)d_in[4];
    const float* Wk      = (const float*)d_in[5];
    const float* bk      = (const float*)d_in[6];
    const float* Wv      = (const float*)d_in[7];
    const float* bv      = (const float*)d_in[8];
    float* out = (float*)d_out;

    __half *ITh, *ISh, *Wqh, *Wkh, *Wvh, *Qh, *Kh, *Vth, *Sh, *Ph, *Ah, *Ch;
    float *Af, *Cf;
    cudaGetSymbolAddress((void**)&ITh, g_ITh);
    cudaGetSymbolAddress((void**)&ISh, g_ISh);
    cudaGetSymbolAddress((void**)&Wqh, g_Wqh);
    cudaGetSymbolAddress((void**)&Wkh, g_Wkh);
    cudaGetSymbolAddress((void**)&Wvh, g_Wvh);
    cudaGetSymbolAddress((void**)&Qh,  g_Qh);
    cudaGetSymbolAddress((void**)&Kh,  g_Kh);
    cudaGetSymbolAddress((void**)&Vth, g_Vth);
    cudaGetSymbolAddress((void**)&Sh,  g_S);
    cudaGetSymbolAddress((void**)&Ph,  g_P);
    cudaGetSymbolAddress((void**)&Ah,  g_Ah);
    cudaGetSymbolAddress((void**)&Ch,  g_Ch);
    cudaGetSymbolAddress((void**)&Af,  g_A);
    cudaGetSymbolAddress((void**)&Cf,  g_C);

    cudaFuncSetAttribute(hgemm<MODE_QK>,  cudaFuncAttributeMaxDynamicSharedMemorySize, SMEM_TOTAL);
    cudaFuncSetAttribute(hgemm<MODE_VT>,  cudaFuncAttributeMaxDynamicSharedMemorySize, SMEM_TOTAL);
    cudaFuncSetAttribute(hgemm<MODE_SC>,  cudaFuncAttributeMaxDynamicSharedMemorySize, SMEM_TOTAL);
    cudaFuncSetAttribute(hgemm<MODE_PV>,  cudaFuncAttributeMaxDynamicSharedMemorySize, SMEM_TOTAL);
    cudaFuncSetAttribute(hgemm<MODE_FIN>, cudaFuncAttributeMaxDynamicSharedMemorySize, SMEM_TOTAL);

    const float scale = 0.044194173824159216f;  // 1/sqrt(512)
    const long long sQKV = (long long)SEQ * DD;
    const long long sS   = (long long)SEQ * SEQ;

    // input converts
    tohalf_kernel<<<2048, 256>>>(Itime,  ITh, MTOT * DD / 4);
    tohalf_kernel<<<2048, 256>>>(Ispace, ISh, MTOT * DD / 4);
    tohalf_kernel<<<512,  256>>>(Wq, Wqh, 4 * DD * DD / 4);
    tohalf_kernel<<<512,  256>>>(Wk, Wkh, 4 * DD * DD / 4);
    tohalf_kernel<<<512,  256>>>(Wv, Wvh, 4 * DD * DD / 4);

    struct Blk { const __half *q, *kv; int w; float* F; int acc; };
    const Blk blks[4] = {
        { ITh, ITh, 0, Af, 0 },   // FTT
        { ITh, ISh, 2, Af, 1 },   // FTS
        { ISh, ISh, 1, Cf, 0 },   // FSS
        { ISh, ITh, 3, Cf, 1 },   // FST
    };

    for (int i = 0; i < 4; i++) {
        const Blk& b = blks[i];
        const size_t wo = (size_t)b.w * DD * DD;

        dim3 gproj(DD / TN, MTOT / TM, 1);
        hgemm<MODE_QK><<<gproj, NTH, SMEM_TOTAL>>>(
            b.q,  Wqh + wo, Qh, bq + b.w * DD,
            DD, DD, DD, DD, 0, 0, 0, 1.0f, 0);
        hgemm<MODE_QK><<<gproj, NTH, SMEM_TOTAL>>>(
            b.kv, Wkh + wo, Kh, bk + b.w * DD,
            DD, DD, DD, DD, 0, 0, 0, 1.0f, 0);
        hgemm<MODE_VT><<<gproj, NTH, SMEM_TOTAL>>>(
            b.kv, Wvh + wo, Vth, bv + b.w * DD,
            DD, DD, MTOT, DD, 0, 0, 0, 1.0f, 0);

        dim3 gsc(SEQ / TN, SEQ / TM, BATCH);
        hgemm<MODE_SC><<<gsc, NTH, SMEM_TOTAL>>>(
            Qh, Kh, Sh, nullptr,
            DD, DD, SEQ, DD, sQKV, sQKV, sS, scale, 0);

        softmax_kernel<<<MTOT, 256>>>(Sh, Ph);

        // F[z] (+)= P[z] @ Vt[z]^T : A = P (K-contig k=key), B = Vt (K-contig)
        dim3 gpv(DD / TN, SEQ / TM, BATCH);
        hgemm<MODE_PV><<<gpv, NTH, SMEM_TOTAL>>>(
            Ph, Vth, b.F, nullptr,
            SEQ, MTOT, DD, SEQ, sS, SEQ, sQKV, 1.0f, b.acc);
    }

    tohalf_kernel<<<2048, 256>>>(Af, Ah, MTOT * DD / 4);
    tohalf_kernel<<<2048, 256>>>(Cf, Ch, MTOT * DD / 4);

    dim3 gfin(SEQ / TN, SEQ / TM, BATCH);
    hgemm<MODE_FIN><<<gfin, NTH, SMEM_TOTAL>>>(
        Ah, Ch, out, xorigin,
        DD, DD, SEQ, DD, sQKV, sQKV, sS, 1.0f, 0);
}